// round 3
// baseline (speedup 1.0000x reference)
#include <cuda_runtime.h>
#include <math.h>

#define BSZ 2
#define SEQ 2048
#define DMODEL 1024
#define NHEAD 16
#define HDIM 64
#define MROWS (BSZ*SEQ)   // 4096

// Scratch (allowed: __device__ globals, no runtime alloc)
__device__ float g_Q[BSZ*NHEAD*SEQ*HDIM];   // [b][h][n][dd]
__device__ float g_K[BSZ*NHEAD*SEQ*HDIM];
__device__ float g_V[BSZ*NHEAD*SEQ*HDIM];
__device__ float g_Cc[MROWS*DMODEL];        // concat [b*n][h*64+dd]

// ---------------------------------------------------------------------------
// Tiled fp32 GEMM, NT form: C[m][c] = sum_k A[m][k] * W[c][k]
// BM=BN=128, BK=16, 256 threads, 8x8 register tile per thread.
// mode 0: A=X, W selected by blockIdx.z from {W0,W1,W2}; scatter to g_Q/g_K/g_V
//         with head-split layout (h = c & 15, dd = c >> 4).
// mode 1: A=g_Cc (ignores A param), W=W0; plain row-major store to Cout.
// ---------------------------------------------------------------------------
__global__ __launch_bounds__(256) void gemm_kernel(
    const float* __restrict__ A,
    const float* __restrict__ W0, const float* __restrict__ W1,
    const float* __restrict__ W2,
    float* __restrict__ Cout, int mode)
{
    const int K = DMODEL;
    const float* Bw = (mode == 1) ? W0
                    : (blockIdx.z == 0 ? W0 : (blockIdx.z == 1 ? W1 : W2));
    const float* Ap = (mode == 1) ? g_Cc : A;

    __shared__ float As[16][132];
    __shared__ float Bs[16][132];

    const int tid  = threadIdx.x;
    const int trow = tid >> 4;      // 0..15
    const int tcol = tid & 15;      // 0..15
    const int rowBase = blockIdx.y * 128;
    const int colBase = blockIdx.x * 128;

    const float* Aptr = Ap + (size_t)rowBase * K;
    const float* Bptr = Bw + (size_t)colBase * K;

    float acc[8][8];
    #pragma unroll
    for (int i = 0; i < 8; i++)
        #pragma unroll
        for (int j = 0; j < 8; j++) acc[i][j] = 0.f;

    for (int k0 = 0; k0 < K; k0 += 16) {
        // Load 128x16 tiles of A and W (both K-major), transpose into smem.
        #pragma unroll
        for (int ch = 0; ch < 2; ch++) {
            int f  = tid + ch * 256;      // float4 id, 512 total
            int r  = f >> 2;              // 0..127
            int c4 = (f & 3) << 2;        // 0,4,8,12
            float4 va = *(const float4*)(Aptr + (size_t)r * K + k0 + c4);
            float4 vb = *(const float4*)(Bptr + (size_t)r * K + k0 + c4);
            As[c4+0][r] = va.x; As[c4+1][r] = va.y;
            As[c4+2][r] = va.z; As[c4+3][r] = va.w;
            Bs[c4+0][r] = vb.x; Bs[c4+1][r] = vb.y;
            Bs[c4+2][r] = vb.z; Bs[c4+3][r] = vb.w;
        }
        __syncthreads();

        #pragma unroll
        for (int kk = 0; kk < 16; kk++) {
            float4 a0 = *(const float4*)&As[kk][trow*8];
            float4 a1 = *(const float4*)&As[kk][trow*8 + 4];
            float4 b0 = *(const float4*)&Bs[kk][tcol*8];
            float4 b1 = *(const float4*)&Bs[kk][tcol*8 + 4];
            float a[8] = {a0.x,a0.y,a0.z,a0.w,a1.x,a1.y,a1.z,a1.w};
            float b[8] = {b0.x,b0.y,b0.z,b0.w,b1.x,b1.y,b1.z,b1.w};
            #pragma unroll
            for (int i = 0; i < 8; i++)
                #pragma unroll
                for (int j = 0; j < 8; j++)
                    acc[i][j] += a[i] * b[j];
        }
        __syncthreads();
    }

    if (mode == 0) {
        float* dst = (blockIdx.z == 0) ? g_Q : (blockIdx.z == 1 ? g_K : g_V);
        #pragma unroll
        for (int i = 0; i < 8; i++) {
            int m = rowBase + trow*8 + i;
            int b = m >> 11;           // /2048
            int n = m & 2047;
            #pragma unroll
            for (int j = 0; j < 8; j++) {
                int c  = colBase + tcol*8 + j;
                int h  = c & 15;       // inner-factor head split
                int dd = c >> 4;
                dst[((size_t)(((b<<4) + h) * SEQ + n) << 6) + dd] = acc[i][j];
            }
        }
    } else {
        #pragma unroll
        for (int i = 0; i < 8; i++) {
            int m = rowBase + trow*8 + i;
            #pragma unroll
            for (int j = 0; j < 8; j++)
                Cout[(size_t)m * DMODEL + colBase + tcol*8 + j] = acc[i][j];
        }
    }
}

// ---------------------------------------------------------------------------
// Flash attention, fp32. Grid (N/64, B*H), 256 threads (8 warps).
// Warp w owns query rows w*8..w*8+7. Per tile of 64 keys:
//   phase 1: each lane computes S[r][2 cols] (cols 2*lane, 2*lane+1),
//            warp-shuffle row max/sum, online softmax, P -> smem.
//   phase 2: lane accumulates O[r][2 dims] at d0 = 2*lane.
// Writes directly into concat layout (col = h*64 + dd).
// ---------------------------------------------------------------------------
__global__ __launch_bounds__(256) void attn_kernel()
{
    extern __shared__ float sm[];
    const int P = 68;                   // pitch (floats); 272B rows, 16B aligned
    float* Qs = sm;                     // [64][68]
    float* Ks = Qs + 64*P;
    float* Vs = Ks + 64*P;
    float* Ps = Vs + 64*P;

    const int tid  = threadIdx.x;
    const int warp = tid >> 5;
    const int lane = tid & 31;
    const int bh   = blockIdx.y;        // 0..31
    const int q0   = blockIdx.x * 64;

    const float* Qg = g_Q + (size_t)bh * SEQ * HDIM + (size_t)q0 * HDIM;
    const float* Kg = g_K + (size_t)bh * SEQ * HDIM;
    const float* Vg = g_V + (size_t)bh * SEQ * HDIM;

    // Load Q tile (64x64)
    #pragma unroll
    for (int ch = 0; ch < 4; ch++) {
        int f  = tid + ch * 256;        // float4 id, 1024 total
        int r  = f >> 4;
        int c4 = (f & 15) << 2;
        *(float4*)&Qs[r*P + c4] = *(const float4*)(Qg + r*HDIM + c4);
    }

    const int r0 = warp * 8;
    const int c0 = lane * 2;
    const int d0 = lane * 2;

    float m_r[8], l_r[8], o_acc[8][2];
    #pragma unroll
    for (int r = 0; r < 8; r++) {
        m_r[r] = -1e30f; l_r[r] = 0.f;
        o_acc[r][0] = 0.f; o_acc[r][1] = 0.f;
    }

    for (int t = 0; t < SEQ/64; t++) {
        __syncthreads();   // previous phase-2 done with Vs (also orders Q loads, t=0)
        const float* Kt = Kg + (size_t)t * 64 * HDIM;
        const float* Vt = Vg + (size_t)t * 64 * HDIM;
        #pragma unroll
        for (int ch = 0; ch < 4; ch++) {
            int f  = tid + ch * 256;
            int r  = f >> 4;
            int c4 = (f & 15) << 2;
            *(float4*)&Ks[r*P + c4] = *(const float4*)(Kt + r*HDIM + c4);
            *(float4*)&Vs[r*P + c4] = *(const float4*)(Vt + r*HDIM + c4);
        }
        __syncthreads();

        // Phase 1: S = Q K^T for this tile
        float s[8][2];
        #pragma unroll
        for (int r = 0; r < 8; r++) { s[r][0] = 0.f; s[r][1] = 0.f; }
        #pragma unroll
        for (int d = 0; d < HDIM; d += 4) {
            float4 k0v = *(const float4*)&Ks[c0*P + d];
            float4 k1v = *(const float4*)&Ks[(c0+1)*P + d];
            #pragma unroll
            for (int r = 0; r < 8; r++) {
                float4 q = *(const float4*)&Qs[(r0+r)*P + d];
                s[r][0] += q.x*k0v.x + q.y*k0v.y + q.z*k0v.z + q.w*k0v.w;
                s[r][1] += q.x*k1v.x + q.y*k1v.y + q.z*k1v.z + q.w*k1v.w;
            }
        }

        // Online softmax
        const float sc = 0.125f;       // 1/sqrt(64)
        #pragma unroll
        for (int r = 0; r < 8; r++) {
            float s0 = s[r][0] * sc, s1 = s[r][1] * sc;
            float tm = fmaxf(s0, s1);
            #pragma unroll
            for (int off = 16; off; off >>= 1)
                tm = fmaxf(tm, __shfl_xor_sync(0xffffffffu, tm, off));
            float nm   = fmaxf(m_r[r], tm);
            float corr = __expf(m_r[r] - nm);
            float p0 = __expf(s0 - nm);
            float p1 = __expf(s1 - nm);
            float ps = p0 + p1;
            #pragma unroll
            for (int off = 16; off; off >>= 1)
                ps += __shfl_xor_sync(0xffffffffu, ps, off);
            l_r[r] = l_r[r] * corr + ps;
            m_r[r] = nm;
            o_acc[r][0] *= corr; o_acc[r][1] *= corr;
            Ps[(r0+r)*P + c0]     = p0;
            Ps[(r0+r)*P + c0 + 1] = p1;
        }
        __syncwarp();      // P rows are warp-private; warp-level sync suffices

        // Phase 2: O += P V
        #pragma unroll
        for (int c = 0; c < 64; c += 4) {
            float2 v0 = *(const float2*)&Vs[(c+0)*P + d0];
            float2 v1 = *(const float2*)&Vs[(c+1)*P + d0];
            float2 v2 = *(const float2*)&Vs[(c+2)*P + d0];
            float2 v3 = *(const float2*)&Vs[(c+3)*P + d0];
            #pragma unroll
            for (int r = 0; r < 8; r++) {
                float4 pv = *(const float4*)&Ps[(r0+r)*P + c];
                o_acc[r][0] += pv.x*v0.x + pv.y*v1.x + pv.z*v2.x + pv.w*v3.x;
                o_acc[r][1] += pv.x*v0.y + pv.y*v1.y + pv.z*v2.y + pv.w*v3.y;
            }
        }
    }

    // Normalize and write to concat layout: concat[b, n, h*64 + dd]
    const int b = bh >> 4;
    const int h = bh & 15;
    #pragma unroll
    for (int r = 0; r < 8; r++) {
        float inv = 1.0f / l_r[r];
        int n = q0 + r0 + r;
        size_t idx = (size_t)(b * SEQ + n) * DMODEL + h * HDIM + d0;
        float2 o2 = make_float2(o_acc[r][0] * inv, o_acc[r][1] * inv);
        *(float2*)&g_Cc[idx] = o2;
    }
}

extern "C" void kernel_launch(void* const* d_in, const int* in_sizes, int n_in,
                              void* d_out, int out_size)
{
    const float* x  = (const float*)d_in[0];
    const float* wq = (const float*)d_in[1];
    const float* wk = (const float*)d_in[2];
    const float* wv = (const float*)d_in[3];
    const float* wo = (const float*)d_in[4];
    float* out = (float*)d_out;

    const int ATTN_SMEM = 4 * 64 * 68 * sizeof(float);  // 69632 bytes
    cudaFuncSetAttribute(attn_kernel,
                         cudaFuncAttributeMaxDynamicSharedMemorySize, ATTN_SMEM);

    // 1) QKV projections with head-split scatter
    gemm_kernel<<<dim3(DMODEL/128, MROWS/128, 3), 256>>>(
        x, wq, wk, wv, nullptr, 0);

    // 2) Flash attention -> concat
    attn_kernel<<<dim3(SEQ/64, BSZ*NHEAD), 256, ATTN_SMEM>>>();

    // 3) Output projection
    gemm_kernel<<<dim3(DMODEL/128, MROWS/128, 1), 256>>>(
        nullptr, wo, nullptr, nullptr, out, 1);
}

// round 5
// speedup vs baseline: 1.8359x; 1.8359x over previous
#include <cuda_runtime.h>
#include <cstdint>
#include <math.h>

#define BSZ 2
#define SEQ 2048
#define DMODEL 1024
#define NHEAD 16
#define HDIM 64
#define MROWS (BSZ*SEQ)   // 4096

// Scratch (allowed: __device__ globals, no runtime alloc)
__device__ float g_Q[BSZ*NHEAD*SEQ*HDIM];   // [b][h][n][dd]
__device__ float g_K[BSZ*NHEAD*SEQ*HDIM];
__device__ float g_V[BSZ*NHEAD*SEQ*HDIM];
__device__ float g_Cc[MROWS*DMODEL];        // concat [b*n][h*64+dd]

// ---------------------------------------------------------------------------
// mma.sync helpers (portable PTX, works on plain compute_103 target)
// ---------------------------------------------------------------------------
__device__ __forceinline__ uint32_t f2tf(float x) {
    uint32_t r;
    asm("cvt.rna.tf32.f32 %0, %1;" : "=r"(r) : "f"(x));
    return r;
}

// D += A(16x8) * B(8x8), tf32 inputs, fp32 accum.
__device__ __forceinline__ void mma_tf32(float* d, const uint32_t* a,
                                         uint32_t b0, uint32_t b1) {
    asm volatile(
        "mma.sync.aligned.m16n8k8.row.col.f32.tf32.tf32.f32 "
        "{%0,%1,%2,%3}, {%4,%5,%6,%7}, {%8,%9}, {%0,%1,%2,%3};"
        : "+f"(d[0]), "+f"(d[1]), "+f"(d[2]), "+f"(d[3])
        : "r"(a[0]), "r"(a[1]), "r"(a[2]), "r"(a[3]), "r"(b0), "r"(b1));
}

// hi/lo tf32 split of 4 floats -> two uint4
__device__ __forceinline__ void split4(float4 v, uint4& H, uint4& L) {
    H.x = f2tf(v.x); L.x = f2tf(v.x - __uint_as_float(H.x));
    H.y = f2tf(v.y); L.y = f2tf(v.y - __uint_as_float(H.y));
    H.z = f2tf(v.z); L.z = f2tf(v.z - __uint_as_float(H.z));
    H.w = f2tf(v.w); L.w = f2tf(v.w - __uint_as_float(H.w));
}

// ===========================================================================
// 3xTF32 GEMM: C[m][c] = sum_k A[m][k] * W[c][k]   (NT, K=1024)
// BM=BN=128, BK=16, 256 threads (8 warps, 4x2 warp grid, warp tile 32x64).
// smem tiles pitch 20 (conflict-free fragment loads). Double-buffered.
// mode 0: A=x, W by blockIdx.z in {wq,wk,wv}; head-split scatter to g_Q/K/V.
// mode 1: A=g_Cc, W=wo; row-major store to out.
// ===========================================================================
#define GEMM_SMEM (2*4*128*20*4)   // 81920 B: 2 stages x {Ah,Al,Wh,Wl}

__global__ __launch_bounds__(256) void gemm_tc32(
    const float* __restrict__ x,
    const float* __restrict__ wq, const float* __restrict__ wk,
    const float* __restrict__ wv, const float* __restrict__ wo,
    float* __restrict__ out, int mode)
{
    extern __shared__ uint32_t smu[];
    const int TILE = 128 * 20;              // floats per tile
    const int STAGE = 4 * TILE;

    const int tid = threadIdx.x;
    const int wid = tid >> 5;
    const int lane = tid & 31;
    const int gid = lane >> 2;              // 0..7
    const int tig = lane & 3;               // 0..3
    const int wm = wid & 3;                 // 0..3
    const int wn = wid >> 2;                // 0..1
    const int rowBase = blockIdx.y * 128;
    const int colBase = blockIdx.x * 128;

    const float* A = (mode == 1) ? (const float*)g_Cc : x;
    const float* W = (mode == 1) ? wo
                   : (blockIdx.z == 0 ? wq : (blockIdx.z == 1 ? wk : wv));
    const float* Aptr = A + (size_t)rowBase * DMODEL;
    const float* Wptr = W + (size_t)colBase * DMODEL;

    float acc[2][8][4];
    #pragma unroll
    for (int i = 0; i < 2; i++)
        #pragma unroll
        for (int j = 0; j < 8; j++)
            #pragma unroll
            for (int q = 0; q < 4; q++) acc[i][j][q] = 0.f;

    // staging regs for one chunk
    float4 av[2], wv4[2];
    const int r0 = tid >> 2;                 // 0..63  (iter adds +64)
    const int q4 = (tid & 3) << 2;           // 0,4,8,12

    // load chunk 0
    av[0]  = *(const float4*)(Aptr + (size_t)r0 * DMODEL + q4);
    av[1]  = *(const float4*)(Aptr + (size_t)(r0 + 64) * DMODEL + q4);
    wv4[0] = *(const float4*)(Wptr + (size_t)r0 * DMODEL + q4);
    wv4[1] = *(const float4*)(Wptr + (size_t)(r0 + 64) * DMODEL + q4);

    #pragma unroll 1
    for (int c = 0; c < 64; c++) {
        const int st = (c & 1) * STAGE;
        uint32_t* Ah = smu + st;
        uint32_t* Al = Ah + TILE;
        uint32_t* Wh = Al + TILE;
        uint32_t* Wl = Wh + TILE;

        // store staged chunk c (split to hi/lo tf32)
        #pragma unroll
        for (int it = 0; it < 2; it++) {
            uint4 H, L;
            int rr = r0 + it * 64;
            split4(av[it], H, L);
            *(uint4*)&Ah[rr * 20 + q4] = H;
            *(uint4*)&Al[rr * 20 + q4] = L;
            split4(wv4[it], H, L);
            *(uint4*)&Wh[rr * 20 + q4] = H;
            *(uint4*)&Wl[rr * 20 + q4] = L;
        }
        __syncthreads();

        // prefetch chunk c+1
        if (c < 63) {
            const int k0 = (c + 1) * 16;
            av[0]  = *(const float4*)(Aptr + (size_t)r0 * DMODEL + k0 + q4);
            av[1]  = *(const float4*)(Aptr + (size_t)(r0 + 64) * DMODEL + k0 + q4);
            wv4[0] = *(const float4*)(Wptr + (size_t)r0 * DMODEL + k0 + q4);
            wv4[1] = *(const float4*)(Wptr + (size_t)(r0 + 64) * DMODEL + k0 + q4);
        }

        // compute on chunk c
        #pragma unroll
        for (int ks = 0; ks < 2; ks++) {
            const int ck = ks * 8 + tig;
            uint32_t ah[2][4], al[2][4];
            #pragma unroll
            for (int mt = 0; mt < 2; mt++) {
                int rm = wm * 32 + mt * 16 + gid;
                ah[mt][0] = Ah[rm * 20 + ck];
                ah[mt][1] = Ah[(rm + 8) * 20 + ck];
                ah[mt][2] = Ah[rm * 20 + ck + 4];
                ah[mt][3] = Ah[(rm + 8) * 20 + ck + 4];
                al[mt][0] = Al[rm * 20 + ck];
                al[mt][1] = Al[(rm + 8) * 20 + ck];
                al[mt][2] = Al[rm * 20 + ck + 4];
                al[mt][3] = Al[(rm + 8) * 20 + ck + 4];
            }
            #pragma unroll
            for (int nt = 0; nt < 8; nt++) {
                int cn = wn * 64 + nt * 8 + gid;
                uint32_t bh0 = Wh[cn * 20 + ck], bh1 = Wh[cn * 20 + ck + 4];
                uint32_t bl0 = Wl[cn * 20 + ck], bl1 = Wl[cn * 20 + ck + 4];
                #pragma unroll
                for (int mt = 0; mt < 2; mt++) {
                    mma_tf32(acc[mt][nt], ah[mt], bh0, bh1);  // hi*hi
                    mma_tf32(acc[mt][nt], ah[mt], bl0, bl1);  // hi*lo
                    mma_tf32(acc[mt][nt], al[mt], bh0, bh1);  // lo*hi
                }
            }
        }
        __syncthreads();
    }

    // Epilogue: fragment (mt, nt): rows rowBase+wm*32+mt*16+{gid,gid+8},
    // cols colBase+wn*64+nt*8+{2tig, 2tig+1}
    if (mode == 0) {
        float* dst = (blockIdx.z == 0) ? g_Q : (blockIdx.z == 1 ? g_K : g_V);
        #pragma unroll
        for (int mt = 0; mt < 2; mt++) {
            #pragma unroll
            for (int fr = 0; fr < 2; fr++) {          // row-lo / row-hi
                int m = rowBase + wm * 32 + mt * 16 + gid + fr * 8;
                int b = m >> 11, n = m & 2047;
                size_t rb = ((size_t)(b << 4)) * SEQ;  // + h*SEQ later
                #pragma unroll
                for (int nt = 0; nt < 8; nt++) {
                    #pragma unroll
                    for (int fc = 0; fc < 2; fc++) {
                        int cc = colBase + wn * 64 + nt * 8 + 2 * tig + fc;
                        int h = cc & 15, dd = cc >> 4;
                        dst[(((rb + (size_t)h * SEQ + n)) << 6) + dd] =
                            acc[mt][nt][fr * 2 + fc];
                    }
                }
            }
        }
    } else {
        #pragma unroll
        for (int mt = 0; mt < 2; mt++) {
            #pragma unroll
            for (int fr = 0; fr < 2; fr++) {
                int m = rowBase + wm * 32 + mt * 16 + gid + fr * 8;
                float* op = out + (size_t)m * DMODEL + colBase + wn * 64;
                #pragma unroll
                for (int nt = 0; nt < 8; nt++) {
                    float2 v = make_float2(acc[mt][nt][fr * 2],
                                           acc[mt][nt][fr * 2 + 1]);
                    *(float2*)&op[nt * 8 + 2 * tig] = v;
                }
            }
        }
    }
}

// ===========================================================================
// Flash attention with tf32 mma.sync. Grid (SEQ/64, B*H), 128 threads (4 warps).
// Warp w: 16 query rows. KV tiles of 64. Q frags resident in registers.
// P never leaves registers (shfl-based C-frag -> A-frag permutation).
// K smem: pitch 68 (conflict-free B-frags). V smem: 64-wide, XOR swizzle.
// ===========================================================================
#define ATTN_SMEM ((64*68 + 64*64) * 4)   // 33792 B

__global__ __launch_bounds__(128) void attn_tc()
{
    extern __shared__ uint32_t smu[];
    uint32_t* Ks = smu;                 // [64][68] tf32 bits
    uint32_t* Vs = smu + 64 * 68;       // [64][64] tf32 bits, xor-swizzled

    const int tid  = threadIdx.x;
    const int w    = tid >> 5;
    const int lane = tid & 31;
    const int G    = lane >> 2;         // 0..7
    const int T    = lane & 3;          // 0..3
    const int bh   = blockIdx.y;        // 0..31
    const int qB   = blockIdx.x * 64;

    const float* Qg = g_Q + (size_t)bh * SEQ * HDIM;
    const float* Kg = g_K + (size_t)bh * SEQ * HDIM;
    const float* Vg = g_V + (size_t)bh * SEQ * HDIM;

    // Q fragments (scaled by 1/8, tf32): qa[kc][0..3]
    uint32_t qa[8][4];
    {
        const int rlo = qB + w * 16 + G;
        #pragma unroll
        for (int kc = 0; kc < 8; kc++) {
            int c0 = kc * 8 + T;
            qa[kc][0] = f2tf(Qg[(size_t)rlo * 64 + c0] * 0.125f);
            qa[kc][1] = f2tf(Qg[(size_t)(rlo + 8) * 64 + c0] * 0.125f);
            qa[kc][2] = f2tf(Qg[(size_t)rlo * 64 + c0 + 4] * 0.125f);
            qa[kc][3] = f2tf(Qg[(size_t)(rlo + 8) * 64 + c0 + 4] * 0.125f);
        }
    }

    float o[8][4];
    #pragma unroll
    for (int nt = 0; nt < 8; nt++)
        #pragma unroll
        for (int q = 0; q < 4; q++) o[nt][q] = 0.f;
    float m_lo = -1e30f, m_hi = -1e30f, l_lo = 0.f, l_hi = 0.f;

    #pragma unroll 1
    for (int t = 0; t < SEQ / 64; t++) {
        __syncthreads();
        // load K,V tile (64x64 each), convert to tf32
        const float* Kt = Kg + (size_t)t * 64 * HDIM;
        const float* Vt = Vg + (size_t)t * 64 * HDIM;
        #pragma unroll
        for (int i = 0; i < 8; i++) {
            int f = tid + i * 128;
            int r = f >> 4;
            int c4 = (f & 15) << 2;
            float4 kv = *(const float4*)(Kt + r * 64 + c4);
            uint4 kb = make_uint4(f2tf(kv.x), f2tf(kv.y), f2tf(kv.z), f2tf(kv.w));
            *(uint4*)&Ks[r * 68 + c4] = kb;
            float4 vv = *(const float4*)(Vt + r * 64 + c4);
            uint4 vb = make_uint4(f2tf(vv.x), f2tf(vv.y), f2tf(vv.z), f2tf(vv.w));
            int pc = c4 ^ ((r & 7) << 3);
            *(uint4*)&Vs[r * 64 + pc] = vb;
        }
        __syncthreads();

        // S = Q K^T (16x64 per warp)
        float s[8][4];
        #pragma unroll
        for (int nt = 0; nt < 8; nt++)
            #pragma unroll
            for (int q = 0; q < 4; q++) s[nt][q] = 0.f;
        #pragma unroll
        for (int kc = 0; kc < 8; kc++) {
            const int ck = kc * 8 + T;
            #pragma unroll
            for (int nt = 0; nt < 8; nt++) {
                uint32_t b0 = Ks[(nt * 8 + G) * 68 + ck];
                uint32_t b1 = Ks[(nt * 8 + G) * 68 + ck + 4];
                mma_tf32(s[nt], qa[kc], b0, b1);
            }
        }

        // online softmax (rows G and G+8 of warp tile)
        float tmx_lo = -1e30f, tmx_hi = -1e30f;
        #pragma unroll
        for (int nt = 0; nt < 8; nt++) {
            tmx_lo = fmaxf(tmx_lo, fmaxf(s[nt][0], s[nt][1]));
            tmx_hi = fmaxf(tmx_hi, fmaxf(s[nt][2], s[nt][3]));
        }
        #pragma unroll
        for (int off = 1; off <= 2; off <<= 1) {
            tmx_lo = fmaxf(tmx_lo, __shfl_xor_sync(0xffffffffu, tmx_lo, off));
            tmx_hi = fmaxf(tmx_hi, __shfl_xor_sync(0xffffffffu, tmx_hi, off));
        }
        float nm_lo = fmaxf(m_lo, tmx_lo), nm_hi = fmaxf(m_hi, tmx_hi);
        float corr_lo = __expf(m_lo - nm_lo), corr_hi = __expf(m_hi - nm_hi);
        m_lo = nm_lo; m_hi = nm_hi;
        float sum_lo = 0.f, sum_hi = 0.f;
        #pragma unroll
        for (int nt = 0; nt < 8; nt++) {
            s[nt][0] = __expf(s[nt][0] - nm_lo);
            s[nt][1] = __expf(s[nt][1] - nm_lo);
            s[nt][2] = __expf(s[nt][2] - nm_hi);
            s[nt][3] = __expf(s[nt][3] - nm_hi);
            sum_lo += s[nt][0] + s[nt][1];
            sum_hi += s[nt][2] + s[nt][3];
            o[nt][0] *= corr_lo; o[nt][1] *= corr_lo;
            o[nt][2] *= corr_hi; o[nt][3] *= corr_hi;
        }
        #pragma unroll
        for (int off = 1; off <= 2; off <<= 1) {
            sum_lo += __shfl_xor_sync(0xffffffffu, sum_lo, off);
            sum_hi += __shfl_xor_sync(0xffffffffu, sum_hi, off);
        }
        l_lo = l_lo * corr_lo + sum_lo;
        l_hi = l_hi * corr_hi + sum_hi;

        // O += P V : build P A-frags via shfl permutation, then mma with V
        #pragma unroll
        for (int g = 0; g < 8; g++) {
            int srcA = (lane & ~3) | (T >> 1);
            int srcB = srcA + 2;
            float e0 = __shfl_sync(0xffffffffu, s[g][0], srcA);
            float e1 = __shfl_sync(0xffffffffu, s[g][1], srcA);
            float e2 = __shfl_sync(0xffffffffu, s[g][2], srcA);
            float e3 = __shfl_sync(0xffffffffu, s[g][3], srcA);
            float f0 = __shfl_sync(0xffffffffu, s[g][0], srcB);
            float f1 = __shfl_sync(0xffffffffu, s[g][1], srcB);
            float f2 = __shfl_sync(0xffffffffu, s[g][2], srcB);
            float f3 = __shfl_sync(0xffffffffu, s[g][3], srcB);
            uint32_t pa[4];
            pa[0] = f2tf((T & 1) ? e1 : e0);   // (row G,   k=T)
            pa[1] = f2tf((T & 1) ? e3 : e2);   // (row G+8, k=T)
            pa[2] = f2tf((T & 1) ? f1 : f0);   // (row G,   k=T+4)
            pa[3] = f2tf((T & 1) ? f3 : f2);   // (row G+8, k=T+4)
            const int cc = (T << 3);           // xor for b0 row (r&7 == T)
            #pragma unroll
            for (int nt = 0; nt < 8; nt++) {
                int col = nt * 8 + G;
                uint32_t b0 = Vs[(g * 8 + T) * 64 + (col ^ cc)];
                uint32_t b1 = Vs[(g * 8 + T + 4) * 64 + (col ^ cc ^ 32)];
                mma_tf32(o[nt], pa, b0, b1);
            }
        }
    }

    // normalize + write to concat layout g_Cc[b*SEQ+n][h*64+dd]
    const int b = bh >> 4, h = bh & 15;
    const int row_lo = qB + w * 16 + G;
    const float il_lo = 1.0f / l_lo, il_hi = 1.0f / l_hi;
    size_t base_lo = ((size_t)(b * SEQ + row_lo)) * DMODEL + h * 64;
    size_t base_hi = base_lo + (size_t)8 * DMODEL;
    #pragma unroll
    for (int nt = 0; nt < 8; nt++) {
        *(float2*)&g_Cc[base_lo + nt * 8 + 2 * T] =
            make_float2(o[nt][0] * il_lo, o[nt][1] * il_lo);
        *(float2*)&g_Cc[base_hi + nt * 8 + 2 * T] =
            make_float2(o[nt][2] * il_hi, o[nt][3] * il_hi);
    }
}

extern "C" void kernel_launch(void* const* d_in, const int* in_sizes, int n_in,
                              void* d_out, int out_size)
{
    const float* x  = (const float*)d_in[0];
    const float* wq = (const float*)d_in[1];
    const float* wk = (const float*)d_in[2];
    const float* wv = (const float*)d_in[3];
    const float* wo = (const float*)d_in[4];
    float* out = (float*)d_out;

    cudaFuncSetAttribute(gemm_tc32,
                         cudaFuncAttributeMaxDynamicSharedMemorySize, GEMM_SMEM);
    cudaFuncSetAttribute(attn_tc,
                         cudaFuncAttributeMaxDynamicSharedMemorySize, ATTN_SMEM);

    // 1) QKV projections (3xTF32) with head-split scatter
    gemm_tc32<<<dim3(DMODEL/128, MROWS/128, 3), 256, GEMM_SMEM>>>(
        x, wq, wk, wv, wo, nullptr, 0);

    // 2) Flash attention (tf32 mma) -> concat
    attn_tc<<<dim3(SEQ/64, BSZ*NHEAD), 128, ATTN_SMEM>>>();

    // 3) Output projection (3xTF32) -> d_out
    gemm_tc32<<<dim3(DMODEL/128, MROWS/128, 1), 256, GEMM_SMEM>>>(
        x, wq, wk, wv, wo, out, 1);
}

// round 6
// speedup vs baseline: 2.6263x; 1.4305x over previous
#include <cuda_runtime.h>
#include <cuda_bf16.h>
#include <cstdint>
#include <math.h>

#define BSZ 2
#define SEQ 2048
#define DMODEL 1024
#define NHEAD 16
#define HDIM 64
#define MROWS (BSZ*SEQ)   // 4096

// Scratch (allowed: __device__ globals, no runtime alloc)
__device__ float g_Q[BSZ*NHEAD*SEQ*HDIM];   // [b][h][n][dd]
__device__ float g_K[BSZ*NHEAD*SEQ*HDIM];
__device__ float g_V[BSZ*NHEAD*SEQ*HDIM];
__device__ float g_Cc[MROWS*DMODEL];        // concat [b*n][h*64+dd]

// ---------------------------------------------------------------------------
// mma.sync helpers (portable PTX on plain compute_103 target)
// ---------------------------------------------------------------------------
__device__ __forceinline__ uint32_t f2tf(float x) {
    uint32_t r;
    asm("cvt.rna.tf32.f32 %0, %1;" : "=r"(r) : "f"(x));
    return r;
}

// tf32: D += A(16x8) * B(8x8)
__device__ __forceinline__ void mma_tf32(float* d, const uint32_t* a,
                                         uint32_t b0, uint32_t b1) {
    asm volatile(
        "mma.sync.aligned.m16n8k8.row.col.f32.tf32.tf32.f32 "
        "{%0,%1,%2,%3}, {%4,%5,%6,%7}, {%8,%9}, {%0,%1,%2,%3};"
        : "+f"(d[0]), "+f"(d[1]), "+f"(d[2]), "+f"(d[3])
        : "r"(a[0]), "r"(a[1]), "r"(a[2]), "r"(a[3]), "r"(b0), "r"(b1));
}

// bf16: D += A(16x16) * B(16x8)
__device__ __forceinline__ void mma_bf16(float* d, const uint32_t* a,
                                         uint32_t b0, uint32_t b1) {
    asm volatile(
        "mma.sync.aligned.m16n8k16.row.col.f32.bf16.bf16.f32 "
        "{%0,%1,%2,%3}, {%4,%5,%6,%7}, {%8,%9}, {%0,%1,%2,%3};"
        : "+f"(d[0]), "+f"(d[1]), "+f"(d[2]), "+f"(d[3])
        : "r"(a[0]), "r"(a[1]), "r"(a[2]), "r"(a[3]), "r"(b0), "r"(b1));
}

// (a,b) fp32 -> packed bf16x2 hi word + bf16x2 lo-residual word
__device__ __forceinline__ void split_pair(float a, float b,
                                           uint32_t& H, uint32_t& L) {
    __nv_bfloat16 ha = __float2bfloat16(a);
    __nv_bfloat16 hb = __float2bfloat16(b);
    __nv_bfloat16 la = __float2bfloat16(a - __bfloat162float(ha));
    __nv_bfloat16 lb = __float2bfloat16(b - __bfloat162float(hb));
    H = (uint32_t)__bfloat16_as_ushort(ha) | ((uint32_t)__bfloat16_as_ushort(hb) << 16);
    L = (uint32_t)__bfloat16_as_ushort(la) | ((uint32_t)__bfloat16_as_ushort(lb) << 16);
}

// ===========================================================================
// 3x-bf16-split GEMM: C[m][c] = sum_k A[m][k] * W[c][k]   (NT, K=1024)
// BM=BN=128, BK=16, 256 threads (8 warps, 4x2 grid, warp tile 32x64).
// Tiles stored as bf16x2 words, row pitch 12 words (banks 12G+T: conflict-
// free for all fragment loads AND loader stores). Double-buffered.
// Per K-chunk(16) per warp: 2mt x 8nt x 3 passes = 48 m16n8k16 MMAs.
// mode 0: A=x, W by blockIdx.z in {wq,wk,wv}; head-split scatter to g_Q/K/V.
// mode 1: A=g_Cc, W=wo; row-major store to out.
// ===========================================================================
#define PITCH 12
#define TILEW (128*PITCH)                 // words per tile
#define GEMM_SMEM (2*4*TILEW*4)           // 49152 B: 2 stages x {Ah,Al,Wh,Wl}

__global__ __launch_bounds__(256, 2) void gemm_bf16s(
    const float* __restrict__ x,
    const float* __restrict__ wq, const float* __restrict__ wk,
    const float* __restrict__ wv, const float* __restrict__ wo,
    float* __restrict__ out, int mode)
{
    extern __shared__ uint32_t smu[];
    const int STAGE = 4 * TILEW;

    const int tid = threadIdx.x;
    const int wid = tid >> 5;
    const int lane = tid & 31;
    const int G = lane >> 2;                // 0..7
    const int T = lane & 3;                 // 0..3
    const int wm = wid & 3;                 // 0..3
    const int wn = wid >> 2;                // 0..1
    const int rowBase = blockIdx.y * 128;
    const int colBase = blockIdx.x * 128;

    const float* A = (mode == 1) ? (const float*)g_Cc : x;
    const float* W = (mode == 1) ? wo
                   : (blockIdx.z == 0 ? wq : (blockIdx.z == 1 ? wk : wv));
    const float* Aptr = A + (size_t)rowBase * DMODEL;
    const float* Wptr = W + (size_t)colBase * DMODEL;

    float acc[2][8][4];
    #pragma unroll
    for (int i = 0; i < 2; i++)
        #pragma unroll
        for (int j = 0; j < 8; j++)
            #pragma unroll
            for (int q = 0; q < 4; q++) acc[i][j][q] = 0.f;

    // loader: thread covers rows r0, r0+64 for A and W; 4 cols at q4
    const int r0 = tid >> 2;                // 0..63
    const int q4 = (tid & 3) << 2;          // 0,4,8,12
    const int wd = (tid & 3) << 1;          // word col 0,2,4,6

    float4 av[2], wv4[2];
    av[0]  = *(const float4*)(Aptr + (size_t)r0 * DMODEL + q4);
    av[1]  = *(const float4*)(Aptr + (size_t)(r0 + 64) * DMODEL + q4);
    wv4[0] = *(const float4*)(Wptr + (size_t)r0 * DMODEL + q4);
    wv4[1] = *(const float4*)(Wptr + (size_t)(r0 + 64) * DMODEL + q4);

    #pragma unroll 1
    for (int c = 0; c < 64; c++) {
        const int st = (c & 1) * STAGE;
        uint32_t* Ah = smu + st;
        uint32_t* Al = Ah + TILEW;
        uint32_t* Wh = Al + TILEW;
        uint32_t* Wl = Wh + TILEW;

        // store staged chunk c (split to bf16 hi/lo, packed words)
        #pragma unroll
        for (int it = 0; it < 2; it++) {
            int rr = r0 + it * 64;
            uint32_t H0, L0, H1, L1;
            split_pair(av[it].x, av[it].y, H0, L0);
            split_pair(av[it].z, av[it].w, H1, L1);
            *(uint2*)&Ah[rr * PITCH + wd] = make_uint2(H0, H1);
            *(uint2*)&Al[rr * PITCH + wd] = make_uint2(L0, L1);
            split_pair(wv4[it].x, wv4[it].y, H0, L0);
            split_pair(wv4[it].z, wv4[it].w, H1, L1);
            *(uint2*)&Wh[rr * PITCH + wd] = make_uint2(H0, H1);
            *(uint2*)&Wl[rr * PITCH + wd] = make_uint2(L0, L1);
        }
        __syncthreads();

        // prefetch chunk c+1
        if (c < 63) {
            const int k0 = (c + 1) * 16;
            av[0]  = *(const float4*)(Aptr + (size_t)r0 * DMODEL + k0 + q4);
            av[1]  = *(const float4*)(Aptr + (size_t)(r0 + 64) * DMODEL + k0 + q4);
            wv4[0] = *(const float4*)(Wptr + (size_t)r0 * DMODEL + k0 + q4);
            wv4[1] = *(const float4*)(Wptr + (size_t)(r0 + 64) * DMODEL + k0 + q4);
        }

        // compute chunk c: one k16 step
        uint32_t ah[2][4], al[2][4];
        #pragma unroll
        for (int mt = 0; mt < 2; mt++) {
            int rm = wm * 32 + mt * 16 + G;
            ah[mt][0] = Ah[rm * PITCH + T];
            ah[mt][1] = Ah[(rm + 8) * PITCH + T];
            ah[mt][2] = Ah[rm * PITCH + T + 4];
            ah[mt][3] = Ah[(rm + 8) * PITCH + T + 4];
            al[mt][0] = Al[rm * PITCH + T];
            al[mt][1] = Al[(rm + 8) * PITCH + T];
            al[mt][2] = Al[rm * PITCH + T + 4];
            al[mt][3] = Al[(rm + 8) * PITCH + T + 4];
        }
        #pragma unroll
        for (int nt = 0; nt < 8; nt++) {
            int cn = wn * 64 + nt * 8 + G;
            uint32_t bh0 = Wh[cn * PITCH + T], bh1 = Wh[cn * PITCH + T + 4];
            uint32_t bl0 = Wl[cn * PITCH + T], bl1 = Wl[cn * PITCH + T + 4];
            #pragma unroll
            for (int mt = 0; mt < 2; mt++) {
                mma_bf16(acc[mt][nt], ah[mt], bh0, bh1);  // hi*hi
                mma_bf16(acc[mt][nt], ah[mt], bl0, bl1);  // hi*lo
                mma_bf16(acc[mt][nt], al[mt], bh0, bh1);  // lo*hi
            }
        }
        __syncthreads();
    }

    // Epilogue: frag (mt,nt): rows rowBase+wm*32+mt*16+{G,G+8},
    // cols colBase+wn*64+nt*8+{2T,2T+1}; acc idx = fr*2+fc.
    if (mode == 0) {
        float* dst = (blockIdx.z == 0) ? g_Q : (blockIdx.z == 1 ? g_K : g_V);
        #pragma unroll
        for (int mt = 0; mt < 2; mt++) {
            #pragma unroll
            for (int fr = 0; fr < 2; fr++) {
                int m = rowBase + wm * 32 + mt * 16 + G + fr * 8;
                int b = m >> 11, n = m & 2047;
                size_t rb = ((size_t)(b << 4)) * SEQ;
                #pragma unroll
                for (int nt = 0; nt < 8; nt++) {
                    #pragma unroll
                    for (int fc = 0; fc < 2; fc++) {
                        int cc = colBase + wn * 64 + nt * 8 + 2 * T + fc;
                        int h = cc & 15, dd = cc >> 4;
                        dst[(((rb + (size_t)h * SEQ + n)) << 6) + dd] =
                            acc[mt][nt][fr * 2 + fc];
                    }
                }
            }
        }
    } else {
        #pragma unroll
        for (int mt = 0; mt < 2; mt++) {
            #pragma unroll
            for (int fr = 0; fr < 2; fr++) {
                int m = rowBase + wm * 32 + mt * 16 + G + fr * 8;
                float* op = out + (size_t)m * DMODEL + colBase + wn * 64;
                #pragma unroll
                for (int nt = 0; nt < 8; nt++)
                    *(float2*)&op[nt * 8 + 2 * T] =
                        make_float2(acc[mt][nt][fr * 2], acc[mt][nt][fr * 2 + 1]);
            }
        }
    }
}

// ===========================================================================
// Flash attention with tf32 mma.sync (unchanged from R5 — passes at 2.85e-4).
// Grid (SEQ/64, B*H), 128 threads (4 warps). Warp: 16 q-rows, KV tiles of 64.
// ===========================================================================
#define ATTN_SMEM ((64*68 + 64*64) * 4)   // 33792 B

__global__ __launch_bounds__(128) void attn_tc()
{
    extern __shared__ uint32_t smu[];
    uint32_t* Ks = smu;                 // [64][68] tf32 bits
    uint32_t* Vs = smu + 64 * 68;       // [64][64] tf32 bits, xor-swizzled

    const int tid  = threadIdx.x;
    const int w    = tid >> 5;
    const int lane = tid & 31;
    const int G    = lane >> 2;
    const int T    = lane & 3;
    const int bh   = blockIdx.y;
    const int qB   = blockIdx.x * 64;

    const float* Qg = g_Q + (size_t)bh * SEQ * HDIM;
    const float* Kg = g_K + (size_t)bh * SEQ * HDIM;
    const float* Vg = g_V + (size_t)bh * SEQ * HDIM;

    uint32_t qa[8][4];
    {
        const int rlo = qB + w * 16 + G;
        #pragma unroll
        for (int kc = 0; kc < 8; kc++) {
            int c0 = kc * 8 + T;
            qa[kc][0] = f2tf(Qg[(size_t)rlo * 64 + c0] * 0.125f);
            qa[kc][1] = f2tf(Qg[(size_t)(rlo + 8) * 64 + c0] * 0.125f);
            qa[kc][2] = f2tf(Qg[(size_t)rlo * 64 + c0 + 4] * 0.125f);
            qa[kc][3] = f2tf(Qg[(size_t)(rlo + 8) * 64 + c0 + 4] * 0.125f);
        }
    }

    float o[8][4];
    #pragma unroll
    for (int nt = 0; nt < 8; nt++)
        #pragma unroll
        for (int q = 0; q < 4; q++) o[nt][q] = 0.f;
    float m_lo = -1e30f, m_hi = -1e30f, l_lo = 0.f, l_hi = 0.f;

    #pragma unroll 1
    for (int t = 0; t < SEQ / 64; t++) {
        __syncthreads();
        const float* Kt = Kg + (size_t)t * 64 * HDIM;
        const float* Vt = Vg + (size_t)t * 64 * HDIM;
        #pragma unroll
        for (int i = 0; i < 8; i++) {
            int f = tid + i * 128;
            int r = f >> 4;
            int c4 = (f & 15) << 2;
            float4 kv = *(const float4*)(Kt + r * 64 + c4);
            uint4 kb = make_uint4(f2tf(kv.x), f2tf(kv.y), f2tf(kv.z), f2tf(kv.w));
            *(uint4*)&Ks[r * 68 + c4] = kb;
            float4 vv = *(const float4*)(Vt + r * 64 + c4);
            uint4 vb = make_uint4(f2tf(vv.x), f2tf(vv.y), f2tf(vv.z), f2tf(vv.w));
            int pc = c4 ^ ((r & 7) << 3);
            *(uint4*)&Vs[r * 64 + pc] = vb;
        }
        __syncthreads();

        float s[8][4];
        #pragma unroll
        for (int nt = 0; nt < 8; nt++)
            #pragma unroll
            for (int q = 0; q < 4; q++) s[nt][q] = 0.f;
        #pragma unroll
        for (int kc = 0; kc < 8; kc++) {
            const int ck = kc * 8 + T;
            #pragma unroll
            for (int nt = 0; nt < 8; nt++) {
                uint32_t b0 = Ks[(nt * 8 + G) * 68 + ck];
                uint32_t b1 = Ks[(nt * 8 + G) * 68 + ck + 4];
                mma_tf32(s[nt], qa[kc], b0, b1);
            }
        }

        float tmx_lo = -1e30f, tmx_hi = -1e30f;
        #pragma unroll
        for (int nt = 0; nt < 8; nt++) {
            tmx_lo = fmaxf(tmx_lo, fmaxf(s[nt][0], s[nt][1]));
            tmx_hi = fmaxf(tmx_hi, fmaxf(s[nt][2], s[nt][3]));
        }
        #pragma unroll
        for (int off = 1; off <= 2; off <<= 1) {
            tmx_lo = fmaxf(tmx_lo, __shfl_xor_sync(0xffffffffu, tmx_lo, off));
            tmx_hi = fmaxf(tmx_hi, __shfl_xor_sync(0xffffffffu, tmx_hi, off));
        }
        float nm_lo = fmaxf(m_lo, tmx_lo), nm_hi = fmaxf(m_hi, tmx_hi);
        float corr_lo = __expf(m_lo - nm_lo), corr_hi = __expf(m_hi - nm_hi);
        m_lo = nm_lo; m_hi = nm_hi;
        float sum_lo = 0.f, sum_hi = 0.f;
        #pragma unroll
        for (int nt = 0; nt < 8; nt++) {
            s[nt][0] = __expf(s[nt][0] - nm_lo);
            s[nt][1] = __expf(s[nt][1] - nm_lo);
            s[nt][2] = __expf(s[nt][2] - nm_hi);
            s[nt][3] = __expf(s[nt][3] - nm_hi);
            sum_lo += s[nt][0] + s[nt][1];
            sum_hi += s[nt][2] + s[nt][3];
            o[nt][0] *= corr_lo; o[nt][1] *= corr_lo;
            o[nt][2] *= corr_hi; o[nt][3] *= corr_hi;
        }
        #pragma unroll
        for (int off = 1; off <= 2; off <<= 1) {
            sum_lo += __shfl_xor_sync(0xffffffffu, sum_lo, off);
            sum_hi += __shfl_xor_sync(0xffffffffu, sum_hi, off);
        }
        l_lo = l_lo * corr_lo + sum_lo;
        l_hi = l_hi * corr_hi + sum_hi;

        #pragma unroll
        for (int g = 0; g < 8; g++) {
            int srcA = (lane & ~3) | (T >> 1);
            int srcB = srcA + 2;
            float e0 = __shfl_sync(0xffffffffu, s[g][0], srcA);
            float e1 = __shfl_sync(0xffffffffu, s[g][1], srcA);
            float e2 = __shfl_sync(0xffffffffu, s[g][2], srcA);
            float e3 = __shfl_sync(0xffffffffu, s[g][3], srcA);
            float f0 = __shfl_sync(0xffffffffu, s[g][0], srcB);
            float f1 = __shfl_sync(0xffffffffu, s[g][1], srcB);
            float f2 = __shfl_sync(0xffffffffu, s[g][2], srcB);
            float f3 = __shfl_sync(0xffffffffu, s[g][3], srcB);
            uint32_t pa[4];
            pa[0] = f2tf((T & 1) ? e1 : e0);
            pa[1] = f2tf((T & 1) ? e3 : e2);
            pa[2] = f2tf((T & 1) ? f1 : f0);
            pa[3] = f2tf((T & 1) ? f3 : f2);
            const int cc = (T << 3);
            #pragma unroll
            for (int nt = 0; nt < 8; nt++) {
                int col = nt * 8 + G;
                uint32_t b0 = Vs[(g * 8 + T) * 64 + (col ^ cc)];
                uint32_t b1 = Vs[(g * 8 + T + 4) * 64 + (col ^ cc ^ 32)];
                mma_tf32(o[nt], pa, b0, b1);
            }
        }
    }

    const int b = bh >> 4, h = bh & 15;
    const int row_lo = qB + w * 16 + G;
    const float il_lo = 1.0f / l_lo, il_hi = 1.0f / l_hi;
    size_t base_lo = ((size_t)(b * SEQ + row_lo)) * DMODEL + h * 64;
    size_t base_hi = base_lo + (size_t)8 * DMODEL;
    #pragma unroll
    for (int nt = 0; nt < 8; nt++) {
        *(float2*)&g_Cc[base_lo + nt * 8 + 2 * T] =
            make_float2(o[nt][0] * il_lo, o[nt][1] * il_lo);
        *(float2*)&g_Cc[base_hi + nt * 8 + 2 * T] =
            make_float2(o[nt][2] * il_hi, o[nt][3] * il_hi);
    }
}

extern "C" void kernel_launch(void* const* d_in, const int* in_sizes, int n_in,
                              void* d_out, int out_size)
{
    const float* x  = (const float*)d_in[0];
    const float* wq = (const float*)d_in[1];
    const float* wk = (const float*)d_in[2];
    const float* wv = (const float*)d_in[3];
    const float* wo = (const float*)d_in[4];
    float* out = (float*)d_out;

    cudaFuncSetAttribute(gemm_bf16s,
                         cudaFuncAttributeMaxDynamicSharedMemorySize, GEMM_SMEM);
    cudaFuncSetAttribute(attn_tc,
                         cudaFuncAttributeMaxDynamicSharedMemorySize, ATTN_SMEM);

    // 1) QKV projections (3x bf16-split) with head-split scatter
    gemm_bf16s<<<dim3(DMODEL/128, MROWS/128, 3), 256, GEMM_SMEM>>>(
        x, wq, wk, wv, wo, nullptr, 0);

    // 2) Flash attention (tf32 mma) -> concat
    attn_tc<<<dim3(SEQ/64, BSZ*NHEAD), 128, ATTN_SMEM>>>();

    // 3) Output projection (3x bf16-split) -> d_out
    gemm_bf16s<<<dim3(DMODEL/128, MROWS/128, 1), 256, GEMM_SMEM>>>(
        x, wq, wk, wv, wo, out, 1);
}

// round 9
// speedup vs baseline: 3.0126x; 1.1471x over previous
#include <cuda_runtime.h>
#include <cuda_bf16.h>
#include <cstdint>
#include <math.h>

#define BSZ 2
#define SEQ 2048
#define DMODEL 1024
#define NHEAD 16
#define HDIM 64
#define MROWS (BSZ*SEQ)   // 4096

// Scratch (allowed: __device__ globals, no runtime alloc)
__device__ float g_Q[BSZ*NHEAD*SEQ*HDIM];   // [b][h][n][dd]
__device__ float g_K[BSZ*NHEAD*SEQ*HDIM];
__device__ float g_V[BSZ*NHEAD*SEQ*HDIM];
__device__ float g_Cc[MROWS*DMODEL];        // concat [b*n][h*64+dd]

// ---------------------------------------------------------------------------
// mma.sync helpers (portable PTX on plain compute_103 target)
// ---------------------------------------------------------------------------
__device__ __forceinline__ uint32_t f2tf(float x) {
    uint32_t r;
    asm("cvt.rna.tf32.f32 %0, %1;" : "=r"(r) : "f"(x));
    return r;
}
// pack two fp32 -> f16x2 (first arg in LOW half)
__device__ __forceinline__ uint32_t ph2(float lo, float hi) {
    uint32_t r;
    asm("cvt.rn.f16x2.f32 %0, %1, %2;" : "=r"(r) : "f"(hi), "f"(lo));
    return r;
}
// tf32: D += A(16x8) * B(8x8)
__device__ __forceinline__ void mma_tf32(float* d, const uint32_t* a,
                                         uint32_t b0, uint32_t b1) {
    asm volatile(
        "mma.sync.aligned.m16n8k8.row.col.f32.tf32.tf32.f32 "
        "{%0,%1,%2,%3}, {%4,%5,%6,%7}, {%8,%9}, {%0,%1,%2,%3};"
        : "+f"(d[0]), "+f"(d[1]), "+f"(d[2]), "+f"(d[3])
        : "r"(a[0]), "r"(a[1]), "r"(a[2]), "r"(a[3]), "r"(b0), "r"(b1));
}
// bf16: D += A(16x16) * B(16x8)
__device__ __forceinline__ void mma_bf16(float* d, const uint32_t* a,
                                         uint32_t b0, uint32_t b1) {
    asm volatile(
        "mma.sync.aligned.m16n8k16.row.col.f32.bf16.bf16.f32 "
        "{%0,%1,%2,%3}, {%4,%5,%6,%7}, {%8,%9}, {%0,%1,%2,%3};"
        : "+f"(d[0]), "+f"(d[1]), "+f"(d[2]), "+f"(d[3])
        : "r"(a[0]), "r"(a[1]), "r"(a[2]), "r"(a[3]), "r"(b0), "r"(b1));
}
// f16: D += A(16x16) * B(16x8)
__device__ __forceinline__ void mma_f16(float* d, const uint32_t* a,
                                        uint32_t b0, uint32_t b1) {
    asm volatile(
        "mma.sync.aligned.m16n8k16.row.col.f32.f16.f16.f32 "
        "{%0,%1,%2,%3}, {%4,%5,%6,%7}, {%8,%9}, {%0,%1,%2,%3};"
        : "+f"(d[0]), "+f"(d[1]), "+f"(d[2]), "+f"(d[3])
        : "r"(a[0]), "r"(a[1]), "r"(a[2]), "r"(a[3]), "r"(b0), "r"(b1));
}
// (a,b) fp32 -> packed bf16x2 hi word + bf16x2 lo-residual word
__device__ __forceinline__ void split_pair(float a, float b,
                                           uint32_t& H, uint32_t& L) {
    __nv_bfloat16 ha = __float2bfloat16(a);
    __nv_bfloat16 hb = __float2bfloat16(b);
    __nv_bfloat16 la = __float2bfloat16(a - __bfloat162float(ha));
    __nv_bfloat16 lb = __float2bfloat16(b - __bfloat162float(hb));
    H = (uint32_t)__bfloat16_as_ushort(ha) | ((uint32_t)__bfloat16_as_ushort(hb) << 16);
    L = (uint32_t)__bfloat16_as_ushort(la) | ((uint32_t)__bfloat16_as_ushort(lb) << 16);
}

// ===========================================================================
// 3x-bf16-split GEMM (unchanged from R6-passing version).
// C[m][c] = sum_k A[m][k] * W[c][k]   (NT, K=1024)
// BM=BN=128, BK=16, 256 threads (8 warps, 4x2 grid, warp tile 32x64).
// Tiles stored as bf16x2 words, row pitch 12 words. Double-buffered.
// mode 0: A=x, W by blockIdx.z in {wq,wk,wv}; head-split scatter to g_Q/K/V.
// mode 1: A=g_Cc, W=wo; row-major store to out.
// ===========================================================================
#define PITCH 12
#define TILEW (128*PITCH)                 // words per tile
#define GEMM_SMEM (2*4*TILEW*4)           // 49152 B

__global__ __launch_bounds__(256, 2) void gemm_bf16s(
    const float* __restrict__ x,
    const float* __restrict__ wq, const float* __restrict__ wk,
    const float* __restrict__ wv, const float* __restrict__ wo,
    float* __restrict__ out, int mode)
{
    extern __shared__ uint32_t smu[];
    const int STAGE = 4 * TILEW;

    const int tid = threadIdx.x;
    const int wid = tid >> 5;
    const int lane = tid & 31;
    const int G = lane >> 2;
    const int T = lane & 3;
    const int wm = wid & 3;
    const int wn = wid >> 2;
    const int rowBase = blockIdx.y * 128;
    const int colBase = blockIdx.x * 128;

    const float* A = (mode == 1) ? (const float*)g_Cc : x;
    const float* W = (mode == 1) ? wo
                   : (blockIdx.z == 0 ? wq : (blockIdx.z == 1 ? wk : wv));
    const float* Aptr = A + (size_t)rowBase * DMODEL;
    const float* Wptr = W + (size_t)colBase * DMODEL;

    float acc[2][8][4];
    #pragma unroll
    for (int i = 0; i < 2; i++)
        #pragma unroll
        for (int j = 0; j < 8; j++)
            #pragma unroll
            for (int q = 0; q < 4; q++) acc[i][j][q] = 0.f;

    const int r0 = tid >> 2;                // 0..63
    const int q4 = (tid & 3) << 2;          // 0,4,8,12
    const int wd = (tid & 3) << 1;          // word col 0,2,4,6

    float4 av[2], wv4[2];
    av[0]  = *(const float4*)(Aptr + (size_t)r0 * DMODEL + q4);
    av[1]  = *(const float4*)(Aptr + (size_t)(r0 + 64) * DMODEL + q4);
    wv4[0] = *(const float4*)(Wptr + (size_t)r0 * DMODEL + q4);
    wv4[1] = *(const float4*)(Wptr + (size_t)(r0 + 64) * DMODEL + q4);

    #pragma unroll 1
    for (int c = 0; c < 64; c++) {
        const int st = (c & 1) * STAGE;
        uint32_t* Ah = smu + st;
        uint32_t* Al = Ah + TILEW;
        uint32_t* Wh = Al + TILEW;
        uint32_t* Wl = Wh + TILEW;

        #pragma unroll
        for (int it = 0; it < 2; it++) {
            int rr = r0 + it * 64;
            uint32_t H0, L0, H1, L1;
            split_pair(av[it].x, av[it].y, H0, L0);
            split_pair(av[it].z, av[it].w, H1, L1);
            *(uint2*)&Ah[rr * PITCH + wd] = make_uint2(H0, H1);
            *(uint2*)&Al[rr * PITCH + wd] = make_uint2(L0, L1);
            split_pair(wv4[it].x, wv4[it].y, H0, L0);
            split_pair(wv4[it].z, wv4[it].w, H1, L1);
            *(uint2*)&Wh[rr * PITCH + wd] = make_uint2(H0, H1);
            *(uint2*)&Wl[rr * PITCH + wd] = make_uint2(L0, L1);
        }
        __syncthreads();

        if (c < 63) {
            const int k0 = (c + 1) * 16;
            av[0]  = *(const float4*)(Aptr + (size_t)r0 * DMODEL + k0 + q4);
            av[1]  = *(const float4*)(Aptr + (size_t)(r0 + 64) * DMODEL + k0 + q4);
            wv4[0] = *(const float4*)(Wptr + (size_t)r0 * DMODEL + k0 + q4);
            wv4[1] = *(const float4*)(Wptr + (size_t)(r0 + 64) * DMODEL + k0 + q4);
        }

        uint32_t ah[2][4], al[2][4];
        #pragma unroll
        for (int mt = 0; mt < 2; mt++) {
            int rm = wm * 32 + mt * 16 + G;
            ah[mt][0] = Ah[rm * PITCH + T];
            ah[mt][1] = Ah[(rm + 8) * PITCH + T];
            ah[mt][2] = Ah[rm * PITCH + T + 4];
            ah[mt][3] = Ah[(rm + 8) * PITCH + T + 4];
            al[mt][0] = Al[rm * PITCH + T];
            al[mt][1] = Al[(rm + 8) * PITCH + T];
            al[mt][2] = Al[rm * PITCH + T + 4];
            al[mt][3] = Al[(rm + 8) * PITCH + T + 4];
        }
        #pragma unroll
        for (int nt = 0; nt < 8; nt++) {
            int cn = wn * 64 + nt * 8 + G;
            uint32_t bh0 = Wh[cn * PITCH + T], bh1 = Wh[cn * PITCH + T + 4];
            uint32_t bl0 = Wl[cn * PITCH + T], bl1 = Wl[cn * PITCH + T + 4];
            #pragma unroll
            for (int mt = 0; mt < 2; mt++) {
                mma_bf16(acc[mt][nt], ah[mt], bh0, bh1);  // hi*hi
                mma_bf16(acc[mt][nt], ah[mt], bl0, bl1);  // hi*lo
                mma_bf16(acc[mt][nt], al[mt], bh0, bh1);  // lo*hi
            }
        }
        __syncthreads();
    }

    if (mode == 0) {
        float* dst = (blockIdx.z == 0) ? g_Q : (blockIdx.z == 1 ? g_K : g_V);
        #pragma unroll
        for (int mt = 0; mt < 2; mt++) {
            #pragma unroll
            for (int fr = 0; fr < 2; fr++) {
                int m = rowBase + wm * 32 + mt * 16 + G + fr * 8;
                int b = m >> 11, n = m & 2047;
                size_t rb = ((size_t)(b << 4)) * SEQ;
                #pragma unroll
                for (int nt = 0; nt < 8; nt++) {
                    #pragma unroll
                    for (int fc = 0; fc < 2; fc++) {
                        int cc = colBase + wn * 64 + nt * 8 + 2 * T + fc;
                        int h = cc & 15, dd = cc >> 4;
                        dst[(((rb + (size_t)h * SEQ + n)) << 6) + dd] =
                            acc[mt][nt][fr * 2 + fc];
                    }
                }
            }
        }
    } else {
        #pragma unroll
        for (int mt = 0; mt < 2; mt++) {
            #pragma unroll
            for (int fr = 0; fr < 2; fr++) {
                int m = rowBase + wm * 32 + mt * 16 + G + fr * 8;
                float* op = out + (size_t)m * DMODEL + colBase + wn * 64;
                #pragma unroll
                for (int nt = 0; nt < 8; nt++)
                    *(float2*)&op[nt * 8 + 2 * T] =
                        make_float2(acc[mt][nt][fr * 2], acc[mt][nt][fr * 2 + 1]);
            }
        }
    }
}

// ===========================================================================
// Flash attention: tf32 S + fp16 PV (FA2 zero-shuffle P fragments).
// Grid (SEQ/64, B*H), 128 threads (4 warps). Warp: 16 q-rows, KV tiles of 64.
// K smem: tf32 [64][68]. V smem: half2 k-pairs [32][72]:
//   Vp[kp][c] = {V[2kp][c], V[2kp+1][c]}  (low half = even key).
// PV B-frag read banks: (8kc+T)*72 + nt*8+G -> 8T+G mod 32: conflict-free.
// Output written fp32 to g_Cc (same as R6).
// ===========================================================================
#define ATTN_SMEM ((64*68 + 32*72) * 4)   // 26624 B

__global__ __launch_bounds__(128) void attn_tc()
{
    extern __shared__ uint32_t smu[];
    uint32_t* Ks = smu;                 // [64][68] tf32 bits
    uint32_t* Vp = smu + 64 * 68;       // [32][72] half2 k-pairs

    const int tid  = threadIdx.x;
    const int w    = tid >> 5;
    const int lane = tid & 31;
    const int G    = lane >> 2;
    const int T    = lane & 3;
    const int bh   = blockIdx.y;        // 0..31
    const int qB   = blockIdx.x * 64;

    const float* Qg = g_Q + (size_t)bh * SEQ * HDIM;
    const float* Kg = g_K + (size_t)bh * SEQ * HDIM;
    const float* Vg = g_V + (size_t)bh * SEQ * HDIM;

    // Q fragments (scaled by 1/8, tf32)
    uint32_t qa[8][4];
    {
        const int rlo = qB + w * 16 + G;
        #pragma unroll
        for (int kc = 0; kc < 8; kc++) {
            int c0 = kc * 8 + T;
            qa[kc][0] = f2tf(Qg[(size_t)rlo * 64 + c0] * 0.125f);
            qa[kc][1] = f2tf(Qg[(size_t)(rlo + 8) * 64 + c0] * 0.125f);
            qa[kc][2] = f2tf(Qg[(size_t)rlo * 64 + c0 + 4] * 0.125f);
            qa[kc][3] = f2tf(Qg[(size_t)(rlo + 8) * 64 + c0 + 4] * 0.125f);
        }
    }

    float o[8][4];
    #pragma unroll
    for (int nt = 0; nt < 8; nt++)
        #pragma unroll
        for (int q = 0; q < 4; q++) o[nt][q] = 0.f;
    float m_lo = -1e30f, m_hi = -1e30f, l_lo = 0.f, l_hi = 0.f;

    #pragma unroll 1
    for (int t = 0; t < SEQ / 64; t++) {
        __syncthreads();
        const float* Kt = Kg + (size_t)t * 64 * HDIM;
        const float* Vt = Vg + (size_t)t * 64 * HDIM;
        // K tile -> tf32 smem
        #pragma unroll
        for (int i = 0; i < 8; i++) {
            int f = tid + i * 128;
            int r = f >> 4;
            int c4 = (f & 15) << 2;
            float4 kv = *(const float4*)(Kt + r * 64 + c4);
            *(uint4*)&Ks[r * 68 + c4] =
                make_uint4(f2tf(kv.x), f2tf(kv.y), f2tf(kv.z), f2tf(kv.w));
        }
        // V tile -> half2 k-pair smem
        #pragma unroll
        for (int i = 0; i < 4; i++) {
            int f = tid + i * 128;
            int kp = f >> 4;
            int c4 = (f & 15) << 2;
            float4 v0 = *(const float4*)(Vt + (2 * kp) * 64 + c4);
            float4 v1 = *(const float4*)(Vt + (2 * kp + 1) * 64 + c4);
            *(uint4*)&Vp[kp * 72 + c4] =
                make_uint4(ph2(v0.x, v1.x), ph2(v0.y, v1.y),
                           ph2(v0.z, v1.z), ph2(v0.w, v1.w));
        }
        __syncthreads();

        // S = Q K^T (16x64 per warp), tf32
        float s[8][4];
        #pragma unroll
        for (int nt = 0; nt < 8; nt++)
            #pragma unroll
            for (int q = 0; q < 4; q++) s[nt][q] = 0.f;
        #pragma unroll
        for (int kc = 0; kc < 8; kc++) {
            const int ck = kc * 8 + T;
            #pragma unroll
            for (int nt = 0; nt < 8; nt++) {
                uint32_t b0 = Ks[(nt * 8 + G) * 68 + ck];
                uint32_t b1 = Ks[(nt * 8 + G) * 68 + ck + 4];
                mma_tf32(s[nt], qa[kc], b0, b1);
            }
        }

        // online softmax (rows G and G+8)
        float tmx_lo = -1e30f, tmx_hi = -1e30f;
        #pragma unroll
        for (int nt = 0; nt < 8; nt++) {
            tmx_lo = fmaxf(tmx_lo, fmaxf(s[nt][0], s[nt][1]));
            tmx_hi = fmaxf(tmx_hi, fmaxf(s[nt][2], s[nt][3]));
        }
        #pragma unroll
        for (int off = 1; off <= 2; off <<= 1) {
            tmx_lo = fmaxf(tmx_lo, __shfl_xor_sync(0xffffffffu, tmx_lo, off));
            tmx_hi = fmaxf(tmx_hi, __shfl_xor_sync(0xffffffffu, tmx_hi, off));
        }
        float nm_lo = fmaxf(m_lo, tmx_lo), nm_hi = fmaxf(m_hi, tmx_hi);
        float corr_lo = __expf(m_lo - nm_lo), corr_hi = __expf(m_hi - nm_hi);
        m_lo = nm_lo; m_hi = nm_hi;
        float sum_lo = 0.f, sum_hi = 0.f;
        #pragma unroll
        for (int nt = 0; nt < 8; nt++) {
            s[nt][0] = __expf(s[nt][0] - nm_lo);
            s[nt][1] = __expf(s[nt][1] - nm_lo);
            s[nt][2] = __expf(s[nt][2] - nm_hi);
            s[nt][3] = __expf(s[nt][3] - nm_hi);
            sum_lo += s[nt][0] + s[nt][1];
            sum_hi += s[nt][2] + s[nt][3];
            o[nt][0] *= corr_lo; o[nt][1] *= corr_lo;
            o[nt][2] *= corr_hi; o[nt][3] *= corr_hi;
        }
        #pragma unroll
        for (int off = 1; off <= 2; off <<= 1) {
            sum_lo += __shfl_xor_sync(0xffffffffu, sum_lo, off);
            sum_hi += __shfl_xor_sync(0xffffffffu, sum_hi, off);
        }
        l_lo = l_lo * corr_lo + sum_lo;
        l_hi = l_hi * corr_hi + sum_hi;

        // O += P V : S C-frag pair-packed IS the f16 A-frag (zero shuffles).
        #pragma unroll
        for (int kc = 0; kc < 4; kc++) {
            uint32_t pa[4];
            pa[0] = ph2(s[2 * kc][0],     s[2 * kc][1]);      // row G,   k 2T,2T+1
            pa[1] = ph2(s[2 * kc][2],     s[2 * kc][3]);      // row G+8
            pa[2] = ph2(s[2 * kc + 1][0], s[2 * kc + 1][1]);  // row G,   k +8
            pa[3] = ph2(s[2 * kc + 1][2], s[2 * kc + 1][3]);  // row G+8
            #pragma unroll
            for (int nt = 0; nt < 8; nt++) {
                int col = nt * 8 + G;
                uint32_t b0 = Vp[(8 * kc + T) * 72 + col];
                uint32_t b1 = Vp[(8 * kc + 4 + T) * 72 + col];
                mma_f16(o[nt], pa, b0, b1);
            }
        }
    }

    // normalize + write fp32 concat g_Cc[b*SEQ+n][h*64+dd]
    const int b = bh >> 4, h = bh & 15;
    const int row_lo = qB + w * 16 + G;
    const float il_lo = 1.0f / l_lo, il_hi = 1.0f / l_hi;
    size_t base_lo = ((size_t)(b * SEQ + row_lo)) * DMODEL + h * 64;
    size_t base_hi = base_lo + (size_t)8 * DMODEL;
    #pragma unroll
    for (int nt = 0; nt < 8; nt++) {
        *(float2*)&g_Cc[base_lo + nt * 8 + 2 * T] =
            make_float2(o[nt][0] * il_lo, o[nt][1] * il_lo);
        *(float2*)&g_Cc[base_hi + nt * 8 + 2 * T] =
            make_float2(o[nt][2] * il_hi, o[nt][3] * il_hi);
    }
}

extern "C" void kernel_launch(void* const* d_in, const int* in_sizes, int n_in,
                              void* d_out, int out_size)
{
    const float* x  = (const float*)d_in[0];
    const float* wq = (const float*)d_in[1];
    const float* wk = (const float*)d_in[2];
    const float* wv = (const float*)d_in[3];
    const float* wo = (const float*)d_in[4];
    float* out = (float*)d_out;

    cudaFuncSetAttribute(gemm_bf16s,
                         cudaFuncAttributeMaxDynamicSharedMemorySize, GEMM_SMEM);
    cudaFuncSetAttribute(attn_tc,
                         cudaFuncAttributeMaxDynamicSharedMemorySize, ATTN_SMEM);

    // 1) QKV projections (3x bf16-split) with head-split scatter
    gemm_bf16s<<<dim3(DMODEL/128, MROWS/128, 3), 256, GEMM_SMEM>>>(
        x, wq, wk, wv, wo, nullptr, 0);

    // 2) Flash attention (tf32 S + fp16 PV) -> concat
    attn_tc<<<dim3(SEQ/64, BSZ*NHEAD), 128, ATTN_SMEM>>>();

    // 3) Output projection (3x bf16-split) -> d_out
    gemm_bf16s<<<dim3(DMODEL/128, MROWS/128, 1), 256, GEMM_SMEM>>>(
        x, wq, wk, wv, wo, out, 1);
}

// round 10
// speedup vs baseline: 3.6832x; 1.2226x over previous
#include <cuda_runtime.h>
#include <cuda_bf16.h>
#include <cstdint>
#include <math.h>

#define BSZ 2
#define SEQ 2048
#define DMODEL 1024
#define NHEAD 16
#define HDIM 64
#define MROWS (BSZ*SEQ)   // 4096

// Scratch (allowed: __device__ globals, no runtime alloc)
__device__ float g_Q[BSZ*NHEAD*SEQ*HDIM];   // [b][h][n][dd]
__device__ float g_K[BSZ*NHEAD*SEQ*HDIM];
__device__ float g_V[BSZ*NHEAD*SEQ*HDIM];
__device__ float g_Cc[MROWS*DMODEL];        // concat [b*n][h*64+dd]

// ---------------------------------------------------------------------------
// mma.sync / ldmatrix helpers (portable PTX on plain compute_103 target)
// ---------------------------------------------------------------------------
// pack two fp32 -> f16x2 (first arg in LOW half)
__device__ __forceinline__ uint32_t ph2(float lo, float hi) {
    uint32_t r;
    asm("cvt.rn.f16x2.f32 %0, %1, %2;" : "=r"(r) : "f"(hi), "f"(lo));
    return r;
}
// bf16: D += A(16x16) * B(16x8)
__device__ __forceinline__ void mma_bf16(float* d, const uint32_t* a,
                                         uint32_t b0, uint32_t b1) {
    asm volatile(
        "mma.sync.aligned.m16n8k16.row.col.f32.bf16.bf16.f32 "
        "{%0,%1,%2,%3}, {%4,%5,%6,%7}, {%8,%9}, {%0,%1,%2,%3};"
        : "+f"(d[0]), "+f"(d[1]), "+f"(d[2]), "+f"(d[3])
        : "r"(a[0]), "r"(a[1]), "r"(a[2]), "r"(a[3]), "r"(b0), "r"(b1));
}
// f16: D += A(16x16) * B(16x8)
__device__ __forceinline__ void mma_f16(float* d, const uint32_t* a,
                                        uint32_t b0, uint32_t b1) {
    asm volatile(
        "mma.sync.aligned.m16n8k16.row.col.f32.f16.f16.f32 "
        "{%0,%1,%2,%3}, {%4,%5,%6,%7}, {%8,%9}, {%0,%1,%2,%3};"
        : "+f"(d[0]), "+f"(d[1]), "+f"(d[2]), "+f"(d[3])
        : "r"(a[0]), "r"(a[1]), "r"(a[2]), "r"(a[3]), "r"(b0), "r"(b1));
}
// ldmatrix x4: four 8x8 b16 matrices, per-lane row addresses
__device__ __forceinline__ void ldm4(uint32_t* r, uint32_t addr) {
    asm volatile(
        "ldmatrix.sync.aligned.m8n8.x4.shared.b16 {%0,%1,%2,%3}, [%4];"
        : "=r"(r[0]), "=r"(r[1]), "=r"(r[2]), "=r"(r[3]) : "r"(addr));
}
__device__ __forceinline__ uint32_t smem_u32(const void* p) {
    uint32_t a;
    asm("{ .reg .u64 t; cvta.to.shared.u64 t, %1; cvt.u32.u64 %0, t; }"
        : "=r"(a) : "l"(p));
    return a;
}
// (a,b) fp32 -> packed bf16x2 hi word + bf16x2 lo-residual word
__device__ __forceinline__ void split_pair(float a, float b,
                                           uint32_t& H, uint32_t& L) {
    __nv_bfloat16 ha = __float2bfloat16(a);
    __nv_bfloat16 hb = __float2bfloat16(b);
    __nv_bfloat16 la = __float2bfloat16(a - __bfloat162float(ha));
    __nv_bfloat16 lb = __float2bfloat16(b - __bfloat162float(hb));
    H = (uint32_t)__bfloat16_as_ushort(ha) | ((uint32_t)__bfloat16_as_ushort(hb) << 16);
    L = (uint32_t)__bfloat16_as_ushort(la) | ((uint32_t)__bfloat16_as_ushort(lb) << 16);
}

// ===========================================================================
// 3x-bf16-split GEMM with ldmatrix fragment loads.
// C[m][c] = sum_k A[m][k] * W[c][k]   (NT, K=1024)
// BM=BN=128, BK=16, 256 threads (8 warps, 4x2 grid, warp tile 32x64).
// Tiles: bf16x2 words, row pitch 12 words (48B, 16B-aligned; ldmatrix rows
// at 12r mod 32 banks -> each phase covers all 32 banks exactly once).
// Double-buffered, ONE __syncthreads per chunk.
// mode 0: A=x, W by blockIdx.z in {wq,wk,wv}; head-split scatter to g_Q/K/V.
// mode 1: A=g_Cc, W=wo; row-major store to out.
// ===========================================================================
#define PITCH 12
#define TILEW (128*PITCH)                 // 1536 words per tile
#define TILEB (TILEW*4)                   // 6144 bytes
#define STAGEB (4*TILEB)                  // 24576 bytes
#define GEMM_SMEM (2*STAGEB)              // 49152 B

__global__ __launch_bounds__(256, 2) void gemm_bf16s(
    const float* __restrict__ x,
    const float* __restrict__ wq, const float* __restrict__ wk,
    const float* __restrict__ wv, const float* __restrict__ wo,
    float* __restrict__ out, int mode)
{
    extern __shared__ uint32_t smu[];
    const uint32_t smb = smem_u32(smu);

    const int tid = threadIdx.x;
    const int wid = tid >> 5;
    const int lane = tid & 31;
    const int G = lane >> 2;
    const int T = lane & 3;
    const int wm = wid & 3;
    const int wn = wid >> 2;
    const int rowBase = blockIdx.y * 128;
    const int colBase = blockIdx.x * 128;

    const float* A = (mode == 1) ? (const float*)g_Cc : x;
    const float* W = (mode == 1) ? wo
                   : (blockIdx.z == 0 ? wq : (blockIdx.z == 1 ? wk : wv));
    const float* Aptr = A + (size_t)rowBase * DMODEL;
    const float* Wptr = W + (size_t)colBase * DMODEL;

    float acc[2][8][4];
    #pragma unroll
    for (int i = 0; i < 2; i++)
        #pragma unroll
        for (int j = 0; j < 8; j++)
            #pragma unroll
            for (int q = 0; q < 4; q++) acc[i][j][q] = 0.f;

    // ldmatrix per-lane byte offsets (within a tile)
    // A (m16k16, x4): row = wm*32 + mt*16 + (lane&15), byte half = (lane>>4)&1
    uint32_t aoff[2];
    #pragma unroll
    for (int mt = 0; mt < 2; mt++)
        aoff[mt] = (uint32_t)((wm * 32 + mt * 16 + (lane & 15)) * PITCH * 4
                              + ((lane >> 4) & 1) * 16);
    // B (two n8k16 frags per x4): rows cn0 + (lane&7) + ((lane>=16)?8:0),
    // byte half = (lane&8)?16:0.  p indexes nt pairs (nt=2p, 2p+1).
    uint32_t boff[4];
    #pragma unroll
    for (int p = 0; p < 4; p++)
        boff[p] = (uint32_t)((wn * 64 + p * 16 + (lane & 7)
                              + ((lane >> 4) & 1) * 8) * PITCH * 4
                             + ((lane & 8) ? 16 : 0));

    const int r0 = tid >> 2;                // 0..63
    const int q4 = (tid & 3) << 2;          // 0,4,8,12
    const int wd = (tid & 3) << 1;          // word col 0,2,4,6

    float4 av[2], wv4[2];
    av[0]  = *(const float4*)(Aptr + (size_t)r0 * DMODEL + q4);
    av[1]  = *(const float4*)(Aptr + (size_t)(r0 + 64) * DMODEL + q4);
    wv4[0] = *(const float4*)(Wptr + (size_t)r0 * DMODEL + q4);
    wv4[1] = *(const float4*)(Wptr + (size_t)(r0 + 64) * DMODEL + q4);

    #pragma unroll 1
    for (int c = 0; c < 64; c++) {
        const uint32_t sbase = smb + (uint32_t)(c & 1) * STAGEB;
        uint32_t* Ah = smu + (c & 1) * (STAGEB / 4);
        uint32_t* Al = Ah + TILEW;
        uint32_t* Wh = Al + TILEW;
        uint32_t* Wl = Wh + TILEW;

        // store staged chunk c (split to bf16 hi/lo, packed words)
        #pragma unroll
        for (int it = 0; it < 2; it++) {
            int rr = r0 + it * 64;
            uint32_t H0, L0, H1, L1;
            split_pair(av[it].x, av[it].y, H0, L0);
            split_pair(av[it].z, av[it].w, H1, L1);
            *(uint2*)&Ah[rr * PITCH + wd] = make_uint2(H0, H1);
            *(uint2*)&Al[rr * PITCH + wd] = make_uint2(L0, L1);
            split_pair(wv4[it].x, wv4[it].y, H0, L0);
            split_pair(wv4[it].z, wv4[it].w, H1, L1);
            *(uint2*)&Wh[rr * PITCH + wd] = make_uint2(H0, H1);
            *(uint2*)&Wl[rr * PITCH + wd] = make_uint2(L0, L1);
        }
        __syncthreads();   // single barrier per chunk (double-buffer safe)

        // prefetch chunk c+1
        if (c < 63) {
            const int k0 = (c + 1) * 16;
            av[0]  = *(const float4*)(Aptr + (size_t)r0 * DMODEL + k0 + q4);
            av[1]  = *(const float4*)(Aptr + (size_t)(r0 + 64) * DMODEL + k0 + q4);
            wv4[0] = *(const float4*)(Wptr + (size_t)r0 * DMODEL + k0 + q4);
            wv4[1] = *(const float4*)(Wptr + (size_t)(r0 + 64) * DMODEL + k0 + q4);
        }

        // fragment loads via ldmatrix (A: 4x, B: 8x per chunk)
        uint32_t ah[2][4], al[2][4];
        ldm4(ah[0], sbase + aoff[0]);
        ldm4(ah[1], sbase + aoff[1]);
        ldm4(al[0], sbase + TILEB + aoff[0]);
        ldm4(al[1], sbase + TILEB + aoff[1]);

        #pragma unroll
        for (int p = 0; p < 4; p++) {
            uint32_t bh[4], bl[4];
            ldm4(bh, sbase + 2 * TILEB + boff[p]);
            ldm4(bl, sbase + 3 * TILEB + boff[p]);
            // nt = 2p uses bh[0],bh[1] / bl[0],bl[1]; nt = 2p+1 uses [2],[3]
            #pragma unroll
            for (int half = 0; half < 2; half++) {
                const int nt = 2 * p + half;
                const uint32_t bh0 = bh[2 * half], bh1 = bh[2 * half + 1];
                const uint32_t bl0 = bl[2 * half], bl1 = bl[2 * half + 1];
                #pragma unroll
                for (int mt = 0; mt < 2; mt++) {
                    mma_bf16(acc[mt][nt], ah[mt], bh0, bh1);  // hi*hi
                    mma_bf16(acc[mt][nt], ah[mt], bl0, bl1);  // hi*lo
                    mma_bf16(acc[mt][nt], al[mt], bh0, bh1);  // lo*hi
                }
            }
        }
        // no trailing sync: store c+1 (other buffer) is safe; store c+2 is
        // ordered after compute c by sync(c+1) + per-warp program order.
    }

    if (mode == 0) {
        float* dst = (blockIdx.z == 0) ? g_Q : (blockIdx.z == 1 ? g_K : g_V);
        #pragma unroll
        for (int mt = 0; mt < 2; mt++) {
            #pragma unroll
            for (int fr = 0; fr < 2; fr++) {
                int m = rowBase + wm * 32 + mt * 16 + G + fr * 8;
                int b = m >> 11, n = m & 2047;
                size_t rb = ((size_t)(b << 4)) * SEQ;
                #pragma unroll
                for (int nt = 0; nt < 8; nt++) {
                    #pragma unroll
                    for (int fc = 0; fc < 2; fc++) {
                        int cc = colBase + wn * 64 + nt * 8 + 2 * T + fc;
                        int h = cc & 15, dd = cc >> 4;
                        dst[(((rb + (size_t)h * SEQ + n)) << 6) + dd] =
                            acc[mt][nt][fr * 2 + fc];
                    }
                }
            }
        }
    } else {
        #pragma unroll
        for (int mt = 0; mt < 2; mt++) {
            #pragma unroll
            for (int fr = 0; fr < 2; fr++) {
                int m = rowBase + wm * 32 + mt * 16 + G + fr * 8;
                float* op = out + (size_t)m * DMODEL + colBase + wn * 64;
                #pragma unroll
                for (int nt = 0; nt < 8; nt++)
                    *(float2*)&op[nt * 8 + 2 * T] =
                        make_float2(acc[mt][nt][fr * 2], acc[mt][nt][fr * 2 + 1]);
            }
        }
    }
}

// ===========================================================================
// Flash attention: fp16 S + fp16 PV (both k16, fp32 accum).
// fp16 mantissa == tf32 mantissa (11 bits), all values range-safe, so this
// is numerically equivalent to the passing tf32 version at half the MMAs.
// Grid (SEQ/64, B*H), 128 threads (4 warps). Warp: 16 q-rows, KV tiles of 64.
// K smem: half2 k-pairs [64 n][36 words]: word j = {K[n][2j], K[n][2j+1]}.
//   S B-frag reads at (nt*8+G)*36 + 8kc+T(+4): banks 4G+T+c -> conflict-free.
// V smem: half2 k-pairs [32][72] (unchanged).
// Per tile: 32 S-MMAs + 32 PV-MMAs (was 64+32).
// ===========================================================================
#define ATTN_SMEM ((64*36 + 32*72) * 4)   // 18432 B

__global__ __launch_bounds__(128) void attn_tc()
{
    extern __shared__ uint32_t smu[];
    uint32_t* Ks = smu;                 // [64][36] half2 k-pairs
    uint32_t* Vp = smu + 64 * 36;       // [32][72] half2 k-pairs

    const int tid  = threadIdx.x;
    const int w    = tid >> 5;
    const int lane = tid & 31;
    const int G    = lane >> 2;
    const int T    = lane & 3;
    const int bh   = blockIdx.y;        // 0..31
    const int qB   = blockIdx.x * 64;

    const float* Qg = g_Q + (size_t)bh * SEQ * HDIM;
    const float* Kg = g_K + (size_t)bh * SEQ * HDIM;
    const float* Vg = g_V + (size_t)bh * SEQ * HDIM;

    // Q fragments (scaled by 1/8), packed fp16 pairs: 4 k16 steps over d=64
    uint32_t qa[4][4];
    {
        const float sc = 0.125f;
        const int rlo = qB + w * 16 + G;
        const float* q0 = Qg + (size_t)rlo * 64;
        const float* q1 = Qg + (size_t)(rlo + 8) * 64;
        #pragma unroll
        for (int kc = 0; kc < 4; kc++) {
            int k = kc * 16 + 2 * T;
            qa[kc][0] = ph2(q0[k] * sc,     q0[k + 1] * sc);
            qa[kc][1] = ph2(q1[k] * sc,     q1[k + 1] * sc);
            qa[kc][2] = ph2(q0[k + 8] * sc, q0[k + 9] * sc);
            qa[kc][3] = ph2(q1[k + 8] * sc, q1[k + 9] * sc);
        }
    }

    float o[8][4];
    #pragma unroll
    for (int nt = 0; nt < 8; nt++)
        #pragma unroll
        for (int q = 0; q < 4; q++) o[nt][q] = 0.f;
    float m_lo = -1e30f, m_hi = -1e30f, l_lo = 0.f, l_hi = 0.f;

    #pragma unroll 1
    for (int t = 0; t < SEQ / 64; t++) {
        __syncthreads();
        const float* Kt = Kg + (size_t)t * 64 * HDIM;
        const float* Vt = Vg + (size_t)t * 64 * HDIM;
        // K tile -> half2 k-pair smem [64][36]
        #pragma unroll
        for (int i = 0; i < 8; i++) {
            int f = tid + i * 128;
            int r = f >> 4;
            int c4 = (f & 15) << 2;          // k base (4 floats)
            float4 kv = *(const float4*)(Kt + r * 64 + c4);
            *(uint2*)&Ks[r * 36 + (c4 >> 1)] =
                make_uint2(ph2(kv.x, kv.y), ph2(kv.z, kv.w));
        }
        // V tile -> half2 k-pair smem [32][72]
        #pragma unroll
        for (int i = 0; i < 4; i++) {
            int f = tid + i * 128;
            int kp = f >> 4;
            int c4 = (f & 15) << 2;
            float4 v0 = *(const float4*)(Vt + (2 * kp) * 64 + c4);
            float4 v1 = *(const float4*)(Vt + (2 * kp + 1) * 64 + c4);
            *(uint4*)&Vp[kp * 72 + c4] =
                make_uint4(ph2(v0.x, v1.x), ph2(v0.y, v1.y),
                           ph2(v0.z, v1.z), ph2(v0.w, v1.w));
        }
        __syncthreads();

        // S = Q K^T (16x64 per warp), fp16 k16: 4 kc x 8 nt = 32 MMAs
        float s[8][4];
        #pragma unroll
        for (int nt = 0; nt < 8; nt++)
            #pragma unroll
            for (int q = 0; q < 4; q++) s[nt][q] = 0.f;
        #pragma unroll
        for (int kc = 0; kc < 4; kc++) {
            #pragma unroll
            for (int nt = 0; nt < 8; nt++) {
                const uint32_t* kr = &Ks[(nt * 8 + G) * 36 + kc * 8 + T];
                mma_f16(s[nt], qa[kc], kr[0], kr[4]);
            }
        }

        // online softmax (rows G and G+8)
        float tmx_lo = -1e30f, tmx_hi = -1e30f;
        #pragma unroll
        for (int nt = 0; nt < 8; nt++) {
            tmx_lo = fmaxf(tmx_lo, fmaxf(s[nt][0], s[nt][1]));
            tmx_hi = fmaxf(tmx_hi, fmaxf(s[nt][2], s[nt][3]));
        }
        #pragma unroll
        for (int off = 1; off <= 2; off <<= 1) {
            tmx_lo = fmaxf(tmx_lo, __shfl_xor_sync(0xffffffffu, tmx_lo, off));
            tmx_hi = fmaxf(tmx_hi, __shfl_xor_sync(0xffffffffu, tmx_hi, off));
        }
        float nm_lo = fmaxf(m_lo, tmx_lo), nm_hi = fmaxf(m_hi, tmx_hi);
        float corr_lo = __expf(m_lo - nm_lo), corr_hi = __expf(m_hi - nm_hi);
        m_lo = nm_lo; m_hi = nm_hi;
        float sum_lo = 0.f, sum_hi = 0.f;
        #pragma unroll
        for (int nt = 0; nt < 8; nt++) {
            s[nt][0] = __expf(s[nt][0] - nm_lo);
            s[nt][1] = __expf(s[nt][1] - nm_lo);
            s[nt][2] = __expf(s[nt][2] - nm_hi);
            s[nt][3] = __expf(s[nt][3] - nm_hi);
            sum_lo += s[nt][0] + s[nt][1];
            sum_hi += s[nt][2] + s[nt][3];
            o[nt][0] *= corr_lo; o[nt][1] *= corr_lo;
            o[nt][2] *= corr_hi; o[nt][3] *= corr_hi;
        }
        #pragma unroll
        for (int off = 1; off <= 2; off <<= 1) {
            sum_lo += __shfl_xor_sync(0xffffffffu, sum_lo, off);
            sum_hi += __shfl_xor_sync(0xffffffffu, sum_hi, off);
        }
        l_lo = l_lo * corr_lo + sum_lo;
        l_hi = l_hi * corr_hi + sum_hi;

        // O += P V : S C-frag pair-packed IS the f16 A-frag (zero shuffles).
        #pragma unroll
        for (int kc = 0; kc < 4; kc++) {
            uint32_t pa[4];
            pa[0] = ph2(s[2 * kc][0],     s[2 * kc][1]);      // row G,   k 2T,2T+1
            pa[1] = ph2(s[2 * kc][2],     s[2 * kc][3]);      // row G+8
            pa[2] = ph2(s[2 * kc + 1][0], s[2 * kc + 1][1]);  // row G,   k +8
            pa[3] = ph2(s[2 * kc + 1][2], s[2 * kc + 1][3]);  // row G+8
            #pragma unroll
            for (int nt = 0; nt < 8; nt++) {
                int col = nt * 8 + G;
                uint32_t b0 = Vp[(8 * kc + T) * 72 + col];
                uint32_t b1 = Vp[(8 * kc + 4 + T) * 72 + col];
                mma_f16(o[nt], pa, b0, b1);
            }
        }
    }

    // normalize + write fp32 concat g_Cc[b*SEQ+n][h*64+dd]
    const int b = bh >> 4, h = bh & 15;
    const int row_lo = qB + w * 16 + G;
    const float il_lo = 1.0f / l_lo, il_hi = 1.0f / l_hi;
    size_t base_lo = ((size_t)(b * SEQ + row_lo)) * DMODEL + h * 64;
    size_t base_hi = base_lo + (size_t)8 * DMODEL;
    #pragma unroll
    for (int nt = 0; nt < 8; nt++) {
        *(float2*)&g_Cc[base_lo + nt * 8 + 2 * T] =
            make_float2(o[nt][0] * il_lo, o[nt][1] * il_lo);
        *(float2*)&g_Cc[base_hi + nt * 8 + 2 * T] =
            make_float2(o[nt][2] * il_hi, o[nt][3] * il_hi);
    }
}

extern "C" void kernel_launch(void* const* d_in, const int* in_sizes, int n_in,
                              void* d_out, int out_size)
{
    const float* x  = (const float*)d_in[0];
    const float* wq = (const float*)d_in[1];
    const float* wk = (const float*)d_in[2];
    const float* wv = (const float*)d_in[3];
    const float* wo = (const float*)d_in[4];
    float* out = (float*)d_out;

    cudaFuncSetAttribute(gemm_bf16s,
                         cudaFuncAttributeMaxDynamicSharedMemorySize, GEMM_SMEM);
    cudaFuncSetAttribute(attn_tc,
                         cudaFuncAttributeMaxDynamicSharedMemorySize, ATTN_SMEM);

    // 1) QKV projections (3x bf16-split, ldmatrix) with head-split scatter
    gemm_bf16s<<<dim3(DMODEL/128, MROWS/128, 3), 256, GEMM_SMEM>>>(
        x, wq, wk, wv, wo, nullptr, 0);

    // 2) Flash attention (fp16 S + fp16 PV) -> concat
    attn_tc<<<dim3(SEQ/64, BSZ*NHEAD), 128, ATTN_SMEM>>>();

    // 3) Output projection (3x bf16-split, ldmatrix) -> d_out
    gemm_bf16s<<<dim3(DMODEL/128, MROWS/128, 1), 256, GEMM_SMEM>>>(
        x, wq, wk, wv, wo, out, 1);
}